// round 9
// baseline (speedup 1.0000x reference)
#include <cuda_runtime.h>
#include <math.h>

#define SQ 2048
#define NB 8
#define HDIM 768
#define HD 384
#define NG 1536
#define NT 64
#define NU 32

// ---------------- device scratch (static, no runtime alloc) ----------------
__device__ float    g_xproj[2u * SQ * NB * NG];   // [dir][t][b][gate_row]  ~201 MB
__device__ float    g_hbuf [8 * 2 * 2 * HD];      // [group][buf][b2][j]
__device__ unsigned g_flag [128 * 32];            // one 128B line per CTA
__device__ float    g_mp   [NB * NU * HDIM];      // [b][u][h] pooled features
__device__ float    g_emb  [NB * NU * HDIM];      // [b][u][h] routed embeddings

// ---------------- f32x2 packed-FMA helpers ---------------------------------
__device__ __forceinline__ unsigned long long fma2(
    unsigned long long a, unsigned long long b, unsigned long long c) {
    unsigned long long d;
    asm("fma.rn.f32x2 %0, %1, %2, %3;" : "=l"(d) : "l"(a), "l"(b), "l"(c));
    return d;
}
__device__ __forceinline__ float2 upk2(unsigned long long v) {
    float2 f;
    asm("mov.b64 {%0,%1}, %2;" : "=f"(f.x), "=f"(f.y) : "l"(v));
    return f;
}
__device__ __forceinline__ unsigned long long pk2(float x, float y) {
    unsigned long long r;
    asm("mov.b64 %0, {%1,%2};" : "=l"(r) : "f"(x), "f"(y));
    return r;
}

// ---------------- pad kernel: 2 pads put k_gemm at launch #4 (ncu) ---------
__global__ void k_pad() {}

// ---------------- flag reset (graph replays must be deterministic) ---------
__global__ void k_reset()
{
    int i = blockIdx.x * 256 + threadIdx.x;
    if (i < 128 * 32) g_flag[i] = 0u;
}

// ---------------- K1: input projection GEMM (both directions) --------------
// xproj[dir][t][b][n] = X[b, s, :] @ Wih_dir^T + bih + bhh   (t = s or S-1-s)
// vs R1: (a) loader remap lr=tid&127 -> conflict-free STS (was 2-way);
//        (b) f32x2 core: row-paired accumulators, a-pairs free from LDS.128.
__global__ void __launch_bounds__(256) k_gemm(
    const float* __restrict__ X,
    const float* __restrict__ Wf, const float* __restrict__ Wb,
    const float* __restrict__ bihf, const float* __restrict__ bhhf,
    const float* __restrict__ bihb, const float* __restrict__ bhhb)
{
    const int dir = blockIdx.z;
    const float* W = dir ? Wb : Wf;
    const int n0 = blockIdx.x * 128;
    const int m0 = blockIdx.y * 128;

    __shared__ __align__(16) float As[8][128];
    __shared__ __align__(16) float Bs[8][128];

    const int tid = threadIdx.x;
    const int lr = tid & 127, lh = tid >> 7;   // loader: conflict-free STS
    const int tx = tid & 15, ty = tid >> 4;    // compute: 16x16 thread grid

    // acc2[p][j] packs rows (2p, 2p+1) of the 8x8 thread tile
    unsigned long long acc2[4][8];
#pragma unroll
    for (int p = 0; p < 4; p++)
#pragma unroll
        for (int j = 0; j < 8; j++) acc2[p][j] = 0ull;

    const float* xptr = X + (m0 + lr) * 768 + lh * 4;
    const float* wptr = W + (n0 + lr) * 768 + lh * 4;

    for (int kt = 0; kt < 768; kt += 8) {
        float4 av = *(const float4*)(xptr + kt);
        float4 bv = *(const float4*)(wptr + kt);
        __syncthreads();
        As[lh * 4 + 0][lr] = av.x; As[lh * 4 + 1][lr] = av.y;
        As[lh * 4 + 2][lr] = av.z; As[lh * 4 + 3][lr] = av.w;
        Bs[lh * 4 + 0][lr] = bv.x; Bs[lh * 4 + 1][lr] = bv.y;
        Bs[lh * 4 + 2][lr] = bv.z; Bs[lh * 4 + 3][lr] = bv.w;
        __syncthreads();
#pragma unroll
        for (int k = 0; k < 8; k++) {
            // a pairs come straight out of LDS.128 (no packing)
            ulonglong2 ap0 = *(const ulonglong2*)&As[k][ty * 8];
            ulonglong2 ap1 = *(const ulonglong2*)&As[k][ty * 8 + 4];
            float4 b0 = *(const float4*)&Bs[k][tx * 8];
            float4 b1 = *(const float4*)&Bs[k][tx * 8 + 4];
            unsigned long long ap[4] = {ap0.x, ap0.y, ap1.x, ap1.y};
            unsigned long long bb[8];
            bb[0] = pk2(b0.x, b0.x); bb[1] = pk2(b0.y, b0.y);
            bb[2] = pk2(b0.z, b0.z); bb[3] = pk2(b0.w, b0.w);
            bb[4] = pk2(b1.x, b1.x); bb[5] = pk2(b1.y, b1.y);
            bb[6] = pk2(b1.z, b1.z); bb[7] = pk2(b1.w, b1.w);
#pragma unroll
            for (int p = 0; p < 4; p++)
#pragma unroll
                for (int j = 0; j < 8; j++)
                    acc2[p][j] = fma2(ap[p], bb[j], acc2[p][j]);
        }
    }

    const float* bi = dir ? bihb : bihf;
    const float* bh = dir ? bhhb : bhhf;
    float bias[8];
#pragma unroll
    for (int j = 0; j < 8; j++) {
        int n = n0 + tx * 8 + j;
        bias[j] = bi[n] + bh[n];
    }
#pragma unroll
    for (int p = 0; p < 4; p++) {
        float rowv[2][8];
#pragma unroll
        for (int j = 0; j < 8; j++) {
            float2 f = upk2(acc2[p][j]);
            rowv[0][j] = f.x + bias[j];
            rowv[1][j] = f.y + bias[j];
        }
#pragma unroll
        for (int h = 0; h < 2; h++) {
            int m = m0 + ty * 8 + p * 2 + h;
            int s = m & 2047, bb2 = m >> 11;
            int t = dir ? (2047 - s) : s;
            float* o = g_xproj + ((((dir * SQ + t) * NB + bb2) * NG) + n0 + tx * 8);
            float4 v0, v1;
            v0.x = rowv[h][0]; v0.y = rowv[h][1];
            v0.z = rowv[h][2]; v0.w = rowv[h][3];
            v1.x = rowv[h][4]; v1.y = rowv[h][5];
            v1.z = rowv[h][6]; v1.w = rowv[h][7];
            *(float4*)(o)     = v0;
            *(float4*)(o + 4) = v1;
        }
    }
}

// ---------------- K2: group-decomposed persistent BiLSTM (R8, unchanged) ---
__global__ void __launch_bounds__(256, 1) k_lstm(
    const float* __restrict__ Whhf, const float* __restrict__ Whhb,
    const int* __restrict__ utter)
{
    const int grp = blockIdx.x >> 4;      // 0..7
    const int c   = blockIdx.x & 15;      // 0..15
    const int dir = grp >> 2;
    const int bp  = grp & 3;              // batches 2bp, 2bp+1
    const int j0  = c * 24;
    const float* Whh = dir ? Whhb : Whhf;
    const int tid = threadIdx.x;
    const int wid = tid >> 5, lane = tid & 31;
    const int g2   = wid >> 1;            // gate 0..3
    const int half = wid & 1;             // unit half
    const int jw   = j0 + half * 12;      // warp's first unit

    __shared__ __align__(16) float h_s[2][HD];   // 2 batches x 384
    __shared__ float gate_s[4][24][2];           // [gate][jj][b2]
    __shared__ float segmax_s[2][33][24];        // [b2][useg][jj]

    for (int i = tid; i < 2 * HD; i += 256) (&h_s[0][0])[i] = 0.f;
    for (int i = tid; i < 2 * 33 * 24; i += 256) (&segmax_s[0][0][0])[i] = 0.f;

    // weights: wp[i][q] = Whh[(g2*HD + jw + i)*HD + lane*2 + 64q]  (f32x2)
    unsigned long long wp[12][6];
#pragma unroll
    for (int i = 0; i < 12; i++) {
        const float* wr = Whh + (long)(g2 * HD + jw + i) * HD + lane * 2;
#pragma unroll
        for (int q = 0; q < 6; q++)
            wp[i][q] = *(const unsigned long long*)(wr + 64 * q);
    }

    const int jj_a = tid >> 1, b2_a = tid & 1;
    const int batch_a = bp * 2 + b2_a;
    float c_state = 0.f;
    unsigned* flags = g_flag + grp * 16 * 32;     // line c at flags + c*32
    float* hbase = g_hbuf + grp * 2 * 2 * HD;     // [buf][b2][j]

    __syncthreads();

    for (int t = 0; t < SQ; t++) {
        // prefetch xproj + utterance id (hidden under the FMA phase)
        float xp0 = 0.f, xp1 = 0.f, xp2 = 0.f, xp3 = 0.f;
        int useg = 0;
        if (tid < 48) {
            int pos = dir ? (SQ - 1 - t) : t;
            const float* xb = g_xproj +
                ((((long)dir * SQ + t) * NB + batch_a) * NG) + j0 + jj_a;
            xp0 = xb[0]; xp1 = xb[HD]; xp2 = xb[2 * HD]; xp3 = xb[3 * HD];
            int u = utter[batch_a * SQ + pos];
            useg = u > 0 ? u : 0;
        }

        // gate partials: 12 rows, batches sequential (shared weights)
#pragma unroll
        for (int b2 = 0; b2 < 2; b2++) {
            unsigned long long p2[12];
#pragma unroll
            for (int i = 0; i < 12; i++) p2[i] = 0ull;
#pragma unroll
            for (int q = 0; q < 6; q++) {
                unsigned long long hq =
                    *(const unsigned long long*)&h_s[b2][lane * 2 + 64 * q];
#pragma unroll
                for (int i = 0; i < 12; i++)
                    p2[i] = fma2(wp[i][q], hq, p2[i]);
            }
#pragma unroll
            for (int i = 0; i < 12; i++) {
                float2 f = upk2(p2[i]);
                float v = f.x + f.y;
                v += __shfl_xor_sync(0xffffffffu, v, 16);
                v += __shfl_xor_sync(0xffffffffu, v, 8);
                v += __shfl_xor_sync(0xffffffffu, v, 4);
                v += __shfl_xor_sync(0xffffffffu, v, 2);
                v += __shfl_xor_sync(0xffffffffu, v, 1);
                if (lane == 0) gate_s[g2][half * 12 + i][b2] = v;
            }
        }
        __syncthreads();

        // activation + publish + fused segment max (MUFU approx)
        if (tid < 48) {
            float vi = gate_s[0][jj_a][b2_a] + xp0;
            float vf = gate_s[1][jj_a][b2_a] + xp1;
            float vg = gate_s[2][jj_a][b2_a] + xp2;
            float vo = gate_s[3][jj_a][b2_a] + xp3;
            float si = 1.f / (1.f + __expf(-vi));
            float sf = 1.f / (1.f + __expf(-vf));
            float so = 1.f / (1.f + __expf(-vo));
            float tg, tc;
            asm("tanh.approx.f32 %0, %1;" : "=f"(tg) : "f"(vg));
            c_state = sf * c_state + si * tg;
            asm("tanh.approx.f32 %0, %1;" : "=f"(tc) : "f"(c_state));
            float h = so * tc;
            __stcg(hbase + (t & 1) * 2 * HD + b2_a * HD + j0 + jj_a, h);
            float* sm = &segmax_s[b2_a][useg][jj_a];
            *sm = fmaxf(*sm, h);
        }
        __syncthreads();

        // group barrier: release-store own line, warp 0 polls 16 lines
        if (tid == 0) {
            asm volatile("st.release.gpu.global.u32 [%0], %1;"
                         :: "l"(flags + c * 32), "r"((unsigned)(t + 1)) : "memory");
        }
        if (wid == 0) {
            unsigned tgt = (unsigned)(t + 1);
            const unsigned* fp = flags + lane * 32;
            bool ok;
            do {
                unsigned v = tgt;
                if (lane < 16)
                    asm volatile("ld.acquire.gpu.global.u32 %0, [%1];"
                                 : "=r"(v) : "l"(fp) : "memory");
                ok = __all_sync(0xffffffffu, v >= tgt);
            } while (!ok);
        }
        __syncthreads();

        // pull the group's hidden state (768 floats, 1 float4 per thread)
        if (tid < 192) {
            const float4* src = (const float4*)(hbase + (t & 1) * 2 * HD);
            ((float4*)(&h_s[0][0]))[tid] = __ldcg(src + tid);
        }
        __syncthreads();
    }

    // emit mp[b][u][dir*384 + j] = max(segmax, 0)  (accumulator init was 0)
    if (tid < 48) {
        for (int u = 1; u <= NU; u++)
            g_mp[(batch_a * NU + (u - 1)) * HDIM + dir * HD + j0 + jj_a] =
                segmax_s[b2_a][u][jj_a];
    }
}

// ---------------- K3: topic softmax routing ---------------------------------
__global__ void __launch_bounds__(256) k_route(
    const float* __restrict__ tw, const float* __restrict__ tb,
    const float* __restrict__ table)
{
    const int b = blockIdx.x >> 5;
    const int u = blockIdx.x & 31;
    __shared__ float mp_s[768];
    __shared__ float lp_s[4][64];
    __shared__ float l_s[64], e_s[64];
    const int tid = threadIdx.x;
    const float* mpr = g_mp + (b * NU + u) * HDIM;
    for (int i = tid; i < 192; i += 256)
        ((float4*)mp_s)[i] = ((const float4*)mpr)[i];
    __syncthreads();
    {
        const int topic = tid & 63, slice = tid >> 6;
        float acc = 0.f;
        const float* wr = tw + topic * 768 + slice * 192;
        const float* ms = mp_s + slice * 192;
        for (int k = 0; k < 192; k += 4) {
            float4 wv = *(const float4*)(wr + k);
            acc = fmaf(wv.x, ms[k], acc);
            acc = fmaf(wv.y, ms[k + 1], acc);
            acc = fmaf(wv.z, ms[k + 2], acc);
            acc = fmaf(wv.w, ms[k + 3], acc);
        }
        lp_s[slice][topic] = acc;
    }
    __syncthreads();
    if (tid < 64)
        l_s[tid] = lp_s[0][tid] + lp_s[1][tid] + lp_s[2][tid] + lp_s[3][tid] + tb[tid];
    __syncthreads();
    if (tid < 64) {
        float mx = -1e30f;
        for (int i = 0; i < 64; i++) mx = fmaxf(mx, l_s[i]);
        e_s[tid] = expf(l_s[tid] - mx);
    }
    __syncthreads();
    float ssum = 0.f;
    for (int i = 0; i < 64; i++) ssum += e_s[i];
    float inv = 1.f / ssum;
    for (int h = tid; h < 768; h += 256) {
        float acc = 0.f;
        for (int tt = 0; tt < 64; tt++)
            acc = fmaf(e_s[tt], table[tt * 768 + h], acc);
        g_emb[(b * NU + u) * HDIM + h] = acc * inv;
    }
}

// ---------------- K4: scatter back to token positions -----------------------
__global__ void __launch_bounds__(256) k_scatter(
    const int* __restrict__ utter, float* __restrict__ out)
{
    int v = blockIdx.x * 256 + threadIdx.x;
    int m = v / 192;
    int h4 = v - m * 192;
    int u = __ldg(utter + m);
    float4 o = make_float4(0.f, 0.f, 0.f, 0.f);
    if (u != 0) {
        int idx = u > 0 ? u - 1 : -u - 1;
        if (idx > 31) idx = 31;
        int bb = m >> 11;
        float4 gv = *(const float4*)(g_emb + (bb * NU + idx) * HDIM + h4 * 4);
        float sc = u > 0 ? 1.f : 2.f;
        o.x = gv.x * sc; o.y = gv.y * sc; o.z = gv.z * sc; o.w = gv.w * sc;
    }
    ((float4*)out)[v] = o;
}

// ---------------- launch -----------------------------------------------------
extern "C" void kernel_launch(void* const* d_in, const int* in_sizes, int n_in,
                              void* d_out, int out_size)
{
    const float* X     = (const float*)d_in[0];
    const float* Wihf  = (const float*)d_in[1];
    const float* Whhf  = (const float*)d_in[2];
    const float* bihf  = (const float*)d_in[3];
    const float* bhhf  = (const float*)d_in[4];
    const float* Wihb  = (const float*)d_in[5];
    const float* Whhb  = (const float*)d_in[6];
    const float* bihb  = (const float*)d_in[7];
    const float* bhhb  = (const float*)d_in[8];
    const float* tw    = (const float*)d_in[9];
    const float* tb    = (const float*)d_in[10];
    const float* table = (const float*)d_in[11];
    const int*   utter = (const int*)d_in[12];

    // 2 pads: ncu capture (launch #4) lands on k_gemm
    k_pad<<<1, 32>>>();
    k_pad<<<1, 32>>>();
    k_reset<<<16, 256>>>();
    k_gemm<<<dim3(12, 128, 2), 256>>>(X, Wihf, Wihb, bihf, bhhf, bihb, bhhb);
    k_lstm<<<128, 256>>>(Whhf, Whhb, utter);
    k_route<<<256, 256>>>(tw, tb, table);
    k_scatter<<<12288, 256>>>(utter, (float*)d_out);
}

// round 10
// speedup vs baseline: 1.0200x; 1.0200x over previous
#include <cuda_runtime.h>
#include <math.h>

#define SQ 2048
#define NB 8
#define HDIM 768
#define HD 384
#define NG 1536
#define NT 64
#define NU 32

// ---------------- device scratch (static, no runtime alloc) ----------------
__device__ float    g_xproj[2u * SQ * NB * NG];   // [dir][t][b][gate_row]
__device__ float    g_hbuf [8 * 2 * 2 * HD];      // fallback path exchange
__device__ unsigned g_flag [128 * 32];            // fallback path flags
__device__ float    g_mp   [NB * NU * HDIM];      // [b][u][h] pooled features
__device__ float    g_emb  [NB * NU * HDIM];      // [b][u][h] routed embeddings

// ---------------- helpers ---------------------------------------------------
__device__ __forceinline__ unsigned long long fma2(
    unsigned long long a, unsigned long long b, unsigned long long c) {
    unsigned long long d;
    asm("fma.rn.f32x2 %0, %1, %2, %3;" : "=l"(d) : "l"(a), "l"(b), "l"(c));
    return d;
}
__device__ __forceinline__ float2 upk2(unsigned long long v) {
    float2 f;
    asm("mov.b64 {%0,%1}, %2;" : "=f"(f.x), "=f"(f.y) : "l"(v));
    return f;
}
__device__ __forceinline__ unsigned smem_u32(const void* p) {
    unsigned a;
    asm("{ .reg .u64 t; cvta.to.shared.u64 t, %1; cvt.u32.u64 %0, t; }"
        : "=r"(a) : "l"(p));
    return a;
}
__device__ __forceinline__ void mbar_wait(unsigned addr, unsigned phase) {
    unsigned done;
    do {
        asm volatile(
            "{\n\t.reg .pred p;\n\t"
            "mbarrier.try_wait.parity.acquire.cta.shared::cta.b64 p, [%1], %2, 0x989680;\n\t"
            "selp.b32 %0, 1, 0, p;\n\t}"
            : "=r"(done) : "r"(addr), "r"(phase) : "memory");
    } while (!done);
}

// ---------------- pad kernel (ncu steering: launch #4 = k_lstm) ------------
__global__ void k_pad() {}

// ---------------- flag reset (fallback path only) --------------------------
__global__ void k_reset()
{
    int i = blockIdx.x * 256 + threadIdx.x;
    if (i < 128 * 32) g_flag[i] = 0u;
}

// ---------------- K1: input projection GEMM (R1/R8 version — known good) ---
__global__ void __launch_bounds__(256) k_gemm(
    const float* __restrict__ X,
    const float* __restrict__ Wf, const float* __restrict__ Wb,
    const float* __restrict__ bihf, const float* __restrict__ bhhf,
    const float* __restrict__ bihb, const float* __restrict__ bhhb)
{
    const int dir = blockIdx.z;
    const float* W = dir ? Wb : Wf;
    const int n0 = blockIdx.x * 128;
    const int m0 = blockIdx.y * 128;

    __shared__ float As[8][128];
    __shared__ float Bs[8][128];

    const int tid = threadIdx.x;
    const int lr = tid >> 1, lh = tid & 1;
    const int tx = tid & 15, ty = tid >> 4;

    float acc[8][8];
#pragma unroll
    for (int i = 0; i < 8; i++)
#pragma unroll
        for (int j = 0; j < 8; j++) acc[i][j] = 0.f;

    const float* xptr = X + (m0 + lr) * 768 + lh * 4;
    const float* wptr = W + (n0 + lr) * 768 + lh * 4;

    for (int kt = 0; kt < 768; kt += 8) {
        float4 av = *(const float4*)(xptr + kt);
        float4 bv = *(const float4*)(wptr + kt);
        __syncthreads();
        As[lh * 4 + 0][lr] = av.x; As[lh * 4 + 1][lr] = av.y;
        As[lh * 4 + 2][lr] = av.z; As[lh * 4 + 3][lr] = av.w;
        Bs[lh * 4 + 0][lr] = bv.x; Bs[lh * 4 + 1][lr] = bv.y;
        Bs[lh * 4 + 2][lr] = bv.z; Bs[lh * 4 + 3][lr] = bv.w;
        __syncthreads();
#pragma unroll
        for (int k = 0; k < 8; k++) {
            float a[8], b[8];
            *(float4*)(a)     = *(const float4*)&As[k][ty * 8];
            *(float4*)(a + 4) = *(const float4*)&As[k][ty * 8 + 4];
            *(float4*)(b)     = *(const float4*)&Bs[k][tx * 8];
            *(float4*)(b + 4) = *(const float4*)&Bs[k][tx * 8 + 4];
#pragma unroll
            for (int i = 0; i < 8; i++)
#pragma unroll
                for (int j = 0; j < 8; j++)
                    acc[i][j] = fmaf(a[i], b[j], acc[i][j]);
        }
    }

    const float* bi = dir ? bihb : bihf;
    const float* bh = dir ? bhhb : bhhf;
    float bias[8];
#pragma unroll
    for (int j = 0; j < 8; j++) {
        int n = n0 + tx * 8 + j;
        bias[j] = bi[n] + bh[n];
    }
#pragma unroll
    for (int i = 0; i < 8; i++) {
        int m = m0 + ty * 8 + i;
        int s = m & 2047, bb = m >> 11;
        int t = dir ? (2047 - s) : s;
        float* o = g_xproj + ((((dir * SQ + t) * NB + bb) * NG) + n0 + tx * 8);
        float4 v0, v1;
        v0.x = acc[i][0] + bias[0]; v0.y = acc[i][1] + bias[1];
        v0.z = acc[i][2] + bias[2]; v0.w = acc[i][3] + bias[3];
        v1.x = acc[i][4] + bias[4]; v1.y = acc[i][5] + bias[5];
        v1.z = acc[i][6] + bias[6]; v1.w = acc[i][7] + bias[7];
        *(float4*)(o)     = v0;
        *(float4*)(o + 4) = v1;
    }
}

// ---------------- K2a: cluster BiLSTM (DSMEM st.async exchange) ------------
// 8 clusters of 16 CTAs = (dir, batch-pair) groups. CTA rank c owns units
// [24c, 24c+24), 4 gates, 2 batches; weights in registers. h exchanged by
// st.async into all 16 peers' double-buffered h_s, completion via mbarrier
// expect_tx (3072B = 16 CTAs x 48 floats). Recurrence dataflow provides
// backpressure; no empty barriers needed.
__global__ void __launch_bounds__(256, 1) __cluster_dims__(16, 1, 1)
k_lstm_cl(const float* __restrict__ Whhf, const float* __restrict__ Whhb,
          const int* __restrict__ utter)
{
    unsigned c;
    asm("mov.u32 %0, %%cluster_ctarank;" : "=r"(c));
    const int grp = blockIdx.x >> 4;
    const int dir = grp >> 2;
    const int bp  = grp & 3;
    const int j0  = (int)c * 24;
    const float* Whh = dir ? Whhb : Whhf;
    const int tid = threadIdx.x;
    const int wid = tid >> 5, lane = tid & 31;
    const int g2   = wid >> 1;
    const int half = wid & 1;
    const int jw   = j0 + half * 12;

    __shared__ __align__(16) float h_s[2][2][HD];   // [buf][b2][j]
    __shared__ float gate_s[4][24][2];
    __shared__ float segmax_s[2][33][24];
    __shared__ __align__(8) unsigned long long mbar[2];

    for (int i = tid; i < 2 * 2 * HD; i += 256) (&h_s[0][0][0])[i] = 0.f;
    for (int i = tid; i < 2 * 33 * 24; i += 256) (&segmax_s[0][0][0])[i] = 0.f;

    const unsigned mb0 = smem_u32(&mbar[0]);
    const unsigned mb1 = smem_u32(&mbar[1]);
    if (tid == 0) {
        asm volatile("mbarrier.init.shared.b64 [%0], %1;" :: "r"(mb0), "r"(1u) : "memory");
        asm volatile("mbarrier.init.shared.b64 [%0], %1;" :: "r"(mb1), "r"(1u) : "memory");
    }
    __syncthreads();
    if (tid == 0) {   // arm both buffers for h(0), h(1)
        asm volatile("mbarrier.arrive.expect_tx.shared.b64 _, [%0], %1;" :: "r"(mb0), "r"(3072u) : "memory");
        asm volatile("mbarrier.arrive.expect_tx.shared.b64 _, [%0], %1;" :: "r"(mb1), "r"(3072u) : "memory");
    }

    // weights: wp[i][q] = Whh[(g2*HD + jw + i)*HD + lane*2 + 64q]  (f32x2)
    unsigned long long wp[12][6];
#pragma unroll
    for (int i = 0; i < 12; i++) {
        const float* wr = Whh + (long)(g2 * HD + jw + i) * HD + lane * 2;
#pragma unroll
        for (int q = 0; q < 6; q++)
            wp[i][q] = *(const unsigned long long*)(wr + 64 * q);
    }

    const int jj_a = tid >> 1, b2_a = tid & 1;
    const int batch_a = bp * 2 + b2_a;
    float c_state = 0.f;

    __syncthreads();
    asm volatile("barrier.cluster.arrive.aligned;" ::: "memory");
    asm volatile("barrier.cluster.wait.aligned;" ::: "memory");

    for (int t = 0; t < SQ; t++) {
        // prefetch xproj + utterance id (overlaps the wait + FMA phase)
        float xp0 = 0.f, xp1 = 0.f, xp2 = 0.f, xp3 = 0.f;
        int useg = 0;
        if (tid < 48) {
            int pos = dir ? (SQ - 1 - t) : t;
            const float* xb = g_xproj +
                ((((long)dir * SQ + t) * NB + batch_a) * NG) + j0 + jj_a;
            xp0 = xb[0]; xp1 = xb[HD]; xp2 = xb[2 * HD]; xp3 = xb[3 * HD];
            int u = utter[batch_a * SQ + pos];
            useg = u > 0 ? u : 0;
        }

        // wait for h(t-1), then re-arm that mbar for h(t+1)
        if (t > 0) {
            unsigned mb = ((t - 1) & 1) ? mb1 : mb0;
            mbar_wait(mb, ((unsigned)(t - 1) >> 1) & 1u);
            if (tid == 0)
                asm volatile("mbarrier.arrive.expect_tx.shared.b64 _, [%0], %1;"
                             :: "r"(mb), "r"(3072u) : "memory");
        }

        // gate FMA on h(t-1) in buf (t+1)&1
        const int br = (t + 1) & 1;
#pragma unroll
        for (int b2 = 0; b2 < 2; b2++) {
            unsigned long long p2[12];
#pragma unroll
            for (int i = 0; i < 12; i++) p2[i] = 0ull;
#pragma unroll
            for (int q = 0; q < 6; q++) {
                unsigned long long hq =
                    *(const unsigned long long*)&h_s[br][b2][lane * 2 + 64 * q];
#pragma unroll
                for (int i = 0; i < 12; i++)
                    p2[i] = fma2(wp[i][q], hq, p2[i]);
            }
#pragma unroll
            for (int i = 0; i < 12; i++) {
                float2 f = upk2(p2[i]);
                float v = f.x + f.y;
                v += __shfl_xor_sync(0xffffffffu, v, 16);
                v += __shfl_xor_sync(0xffffffffu, v, 8);
                v += __shfl_xor_sync(0xffffffffu, v, 4);
                v += __shfl_xor_sync(0xffffffffu, v, 2);
                v += __shfl_xor_sync(0xffffffffu, v, 1);
                if (lane == 0) gate_s[g2][half * 12 + i][b2] = v;
            }
        }
        __syncthreads();

        // activation + DSMEM broadcast + fused segment max
        if (tid < 48) {
            float vi = gate_s[0][jj_a][b2_a] + xp0;
            float vf = gate_s[1][jj_a][b2_a] + xp1;
            float vg = gate_s[2][jj_a][b2_a] + xp2;
            float vo = gate_s[3][jj_a][b2_a] + xp3;
            float si = 1.f / (1.f + __expf(-vi));
            float sf = 1.f / (1.f + __expf(-vf));
            float so = 1.f / (1.f + __expf(-vo));
            float tg, tc;
            asm("tanh.approx.f32 %0, %1;" : "=f"(tg) : "f"(vg));
            c_state = sf * c_state + si * tg;
            asm("tanh.approx.f32 %0, %1;" : "=f"(tc) : "f"(c_state));
            float h = so * tc;

            unsigned val   = __float_as_uint(h);
            unsigned laddr = smem_u32(&h_s[t & 1][b2_a][j0 + jj_a]);
            unsigned lmbar = (t & 1) ? mb1 : mb0;
#pragma unroll
            for (int p = 0; p < 16; p++) {
                unsigned ra, rb;
                asm("mapa.shared::cluster.u32 %0, %1, %2;" : "=r"(ra) : "r"(laddr), "r"(p));
                asm("mapa.shared::cluster.u32 %0, %1, %2;" : "=r"(rb) : "r"(lmbar), "r"(p));
                asm volatile(
                    "st.async.shared::cluster.mbarrier::complete_tx::bytes.u32 [%0], %1, [%2];"
                    :: "r"(ra), "r"(val), "r"(rb) : "memory");
            }
            float* sm = &segmax_s[b2_a][useg][jj_a];
            *sm = fmaxf(*sm, h);
        }
        // no further sync: next-step mbar wait can't pass until our own
        // act threads (which read gate_s) have sent their tx.
    }

    // drain: wait for the final h(2047) tx so no peer writes after our exit
    mbar_wait(mb1, ((unsigned)(SQ - 1) >> 1) & 1u);

    if (tid < 48) {
        for (int u = 1; u <= NU; u++)
            g_mp[(batch_a * NU + (u - 1)) * HDIM + dir * HD + j0 + jj_a] =
                segmax_s[b2_a][u][jj_a];
    }
}

// ---------------- K2b: fallback BiLSTM (R8 version, L2 flag exchange) ------
__global__ void __launch_bounds__(256, 1) k_lstm(
    const float* __restrict__ Whhf, const float* __restrict__ Whhb,
    const int* __restrict__ utter)
{
    const int grp = blockIdx.x >> 4;
    const int c   = blockIdx.x & 15;
    const int dir = grp >> 2;
    const int bp  = grp & 3;
    const int j0  = c * 24;
    const float* Whh = dir ? Whhb : Whhf;
    const int tid = threadIdx.x;
    const int wid = tid >> 5, lane = tid & 31;
    const int g2   = wid >> 1;
    const int half = wid & 1;
    const int jw   = j0 + half * 12;

    __shared__ __align__(16) float h_s[2][HD];
    __shared__ float gate_s[4][24][2];
    __shared__ float segmax_s[2][33][24];

    for (int i = tid; i < 2 * HD; i += 256) (&h_s[0][0])[i] = 0.f;
    for (int i = tid; i < 2 * 33 * 24; i += 256) (&segmax_s[0][0][0])[i] = 0.f;

    unsigned long long wp[12][6];
#pragma unroll
    for (int i = 0; i < 12; i++) {
        const float* wr = Whh + (long)(g2 * HD + jw + i) * HD + lane * 2;
#pragma unroll
        for (int q = 0; q < 6; q++)
            wp[i][q] = *(const unsigned long long*)(wr + 64 * q);
    }

    const int jj_a = tid >> 1, b2_a = tid & 1;
    const int batch_a = bp * 2 + b2_a;
    float c_state = 0.f;
    unsigned* flags = g_flag + grp * 16 * 32;
    float* hbase = g_hbuf + grp * 2 * 2 * HD;

    __syncthreads();

    for (int t = 0; t < SQ; t++) {
        float xp0 = 0.f, xp1 = 0.f, xp2 = 0.f, xp3 = 0.f;
        int useg = 0;
        if (tid < 48) {
            int pos = dir ? (SQ - 1 - t) : t;
            const float* xb = g_xproj +
                ((((long)dir * SQ + t) * NB + batch_a) * NG) + j0 + jj_a;
            xp0 = xb[0]; xp1 = xb[HD]; xp2 = xb[2 * HD]; xp3 = xb[3 * HD];
            int u = utter[batch_a * SQ + pos];
            useg = u > 0 ? u : 0;
        }

#pragma unroll
        for (int b2 = 0; b2 < 2; b2++) {
            unsigned long long p2[12];
#pragma unroll
            for (int i = 0; i < 12; i++) p2[i] = 0ull;
#pragma unroll
            for (int q = 0; q < 6; q++) {
                unsigned long long hq =
                    *(const unsigned long long*)&h_s[b2][lane * 2 + 64 * q];
#pragma unroll
                for (int i = 0; i < 12; i++)
                    p2[i] = fma2(wp[i][q], hq, p2[i]);
            }
#pragma unroll
            for (int i = 0; i < 12; i++) {
                float2 f = upk2(p2[i]);
                float v = f.x + f.y;
                v += __shfl_xor_sync(0xffffffffu, v, 16);
                v += __shfl_xor_sync(0xffffffffu, v, 8);
                v += __shfl_xor_sync(0xffffffffu, v, 4);
                v += __shfl_xor_sync(0xffffffffu, v, 2);
                v += __shfl_xor_sync(0xffffffffu, v, 1);
                if (lane == 0) gate_s[g2][half * 12 + i][b2] = v;
            }
        }
        __syncthreads();

        if (tid < 48) {
            float vi = gate_s[0][jj_a][b2_a] + xp0;
            float vf = gate_s[1][jj_a][b2_a] + xp1;
            float vg = gate_s[2][jj_a][b2_a] + xp2;
            float vo = gate_s[3][jj_a][b2_a] + xp3;
            float si = 1.f / (1.f + __expf(-vi));
            float sf = 1.f / (1.f + __expf(-vf));
            float so = 1.f / (1.f + __expf(-vo));
            float tg, tc;
            asm("tanh.approx.f32 %0, %1;" : "=f"(tg) : "f"(vg));
            c_state = sf * c_state + si * tg;
            asm("tanh.approx.f32 %0, %1;" : "=f"(tc) : "f"(c_state));
            float h = so * tc;
            __stcg(hbase + (t & 1) * 2 * HD + b2_a * HD + j0 + jj_a, h);
            float* sm = &segmax_s[b2_a][useg][jj_a];
            *sm = fmaxf(*sm, h);
        }
        __syncthreads();

        if (tid == 0) {
            asm volatile("st.release.gpu.global.u32 [%0], %1;"
                         :: "l"(flags + c * 32), "r"((unsigned)(t + 1)) : "memory");
        }
        if (wid == 0) {
            unsigned tgt = (unsigned)(t + 1);
            const unsigned* fp = flags + lane * 32;
            bool ok;
            do {
                unsigned v = tgt;
                if (lane < 16)
                    asm volatile("ld.acquire.gpu.global.u32 %0, [%1];"
                                 : "=r"(v) : "l"(fp) : "memory");
                ok = __all_sync(0xffffffffu, v >= tgt);
            } while (!ok);
        }
        __syncthreads();

        if (tid < 192) {
            const float4* src = (const float4*)(hbase + (t & 1) * 2 * HD);
            ((float4*)(&h_s[0][0]))[tid] = __ldcg(src + tid);
        }
        __syncthreads();
    }

    if (tid < 48) {
        for (int u = 1; u <= NU; u++)
            g_mp[(batch_a * NU + (u - 1)) * HDIM + dir * HD + j0 + jj_a] =
                segmax_s[b2_a][u][jj_a];
    }
}

// ---------------- K3: topic softmax routing ---------------------------------
__global__ void __launch_bounds__(256) k_route(
    const float* __restrict__ tw, const float* __restrict__ tb,
    const float* __restrict__ table)
{
    const int b = blockIdx.x >> 5;
    const int u = blockIdx.x & 31;
    __shared__ float mp_s[768];
    __shared__ float lp_s[4][64];
    __shared__ float l_s[64], e_s[64];
    const int tid = threadIdx.x;
    const float* mpr = g_mp + (b * NU + u) * HDIM;
    for (int i = tid; i < 192; i += 256)
        ((float4*)mp_s)[i] = ((const float4*)mpr)[i];
    __syncthreads();
    {
        const int topic = tid & 63, slice = tid >> 6;
        float acc = 0.f;
        const float* wr = tw + topic * 768 + slice * 192;
        const float* ms = mp_s + slice * 192;
        for (int k = 0; k < 192; k += 4) {
            float4 wv = *(const float4*)(wr + k);
            acc = fmaf(wv.x, ms[k], acc);
            acc = fmaf(wv.y, ms[k + 1], acc);
            acc = fmaf(wv.z, ms[k + 2], acc);
            acc = fmaf(wv.w, ms[k + 3], acc);
        }
        lp_s[slice][topic] = acc;
    }
    __syncthreads();
    if (tid < 64)
        l_s[tid] = lp_s[0][tid] + lp_s[1][tid] + lp_s[2][tid] + lp_s[3][tid] + tb[tid];
    __syncthreads();
    if (tid < 64) {
        float mx = -1e30f;
        for (int i = 0; i < 64; i++) mx = fmaxf(mx, l_s[i]);
        e_s[tid] = expf(l_s[tid] - mx);
    }
    __syncthreads();
    float ssum = 0.f;
    for (int i = 0; i < 64; i++) ssum += e_s[i];
    float inv = 1.f / ssum;
    for (int h = tid; h < 768; h += 256) {
        float acc = 0.f;
        for (int tt = 0; tt < 64; tt++)
            acc = fmaf(e_s[tt], table[tt * 768 + h], acc);
        g_emb[(b * NU + u) * HDIM + h] = acc * inv;
    }
}

// ---------------- K4: scatter back to token positions -----------------------
__global__ void __launch_bounds__(256) k_scatter(
    const int* __restrict__ utter, float* __restrict__ out)
{
    int v = blockIdx.x * 256 + threadIdx.x;
    int m = v / 192;
    int h4 = v - m * 192;
    int u = __ldg(utter + m);
    float4 o = make_float4(0.f, 0.f, 0.f, 0.f);
    if (u != 0) {
        int idx = u > 0 ? u - 1 : -u - 1;
        if (idx > 31) idx = 31;
        int bb = m >> 11;
        float4 gv = *(const float4*)(g_emb + (bb * NU + idx) * HDIM + h4 * 4);
        float sc = u > 0 ? 1.f : 2.f;
        o.x = gv.x * sc; o.y = gv.y * sc; o.z = gv.z * sc; o.w = gv.w * sc;
    }
    ((float4*)out)[v] = o;
}

// ---------------- launch -----------------------------------------------------
extern "C" void kernel_launch(void* const* d_in, const int* in_sizes, int n_in,
                              void* d_out, int out_size)
{
    const float* X     = (const float*)d_in[0];
    const float* Wihf  = (const float*)d_in[1];
    const float* Whhf  = (const float*)d_in[2];
    const float* bihf  = (const float*)d_in[3];
    const float* bhhf  = (const float*)d_in[4];
    const float* Wihb  = (const float*)d_in[5];
    const float* Whhb  = (const float*)d_in[6];
    const float* bihb  = (const float*)d_in[7];
    const float* bhhb  = (const float*)d_in[8];
    const float* tw    = (const float*)d_in[9];
    const float* tb    = (const float*)d_in[10];
    const float* table = (const float*)d_in[11];
    const int*   utter = (const int*)d_in[12];

    // capture-safe, deterministic probe: can 8 clusters of 16 be resident?
    cudaFuncSetAttribute(k_lstm_cl,
                         cudaFuncAttributeNonPortableClusterSizeAllowed, 1);
    cudaLaunchConfig_t cfg = {};
    cfg.gridDim  = dim3(128, 1, 1);
    cfg.blockDim = dim3(256, 1, 1);
    cfg.dynamicSmemBytes = 0;
    cfg.stream = 0;
    cudaLaunchAttribute attrs[1];
    attrs[0].id = cudaLaunchAttributeClusterDimension;
    attrs[0].val.clusterDim.x = 16;
    attrs[0].val.clusterDim.y = 1;
    attrs[0].val.clusterDim.z = 1;
    cfg.attrs = attrs;
    cfg.numAttrs = 1;
    int ncl = 0;
    cudaError_t perr = cudaOccupancyMaxActiveClusters(&ncl, k_lstm_cl, &cfg);
    bool use_cl = (perr == cudaSuccess) && (ncl >= 8);
    cudaGetLastError();   // clear any sticky probe error

    // 2 pads: ncu capture (launch #4) lands on the lstm kernel
    k_pad<<<1, 32>>>();
    k_pad<<<1, 32>>>();
    k_gemm<<<dim3(12, 128, 2), 256>>>(X, Wihf, Wihb, bihf, bhhf, bihb, bhhb);
    if (use_cl) {
        k_lstm_cl<<<128, 256>>>(Whhf, Whhb, utter);   // cluster dims from annotation
    } else {
        k_reset<<<16, 256>>>();
        k_lstm<<<128, 256>>>(Whhf, Whhb, utter);
    }
    k_route<<<256, 256>>>(tw, tb, table);
    k_scatter<<<12288, 256>>>(utter, (float*)d_out);
}

// round 11
// speedup vs baseline: 1.0673x; 1.0464x over previous
#include <cuda_runtime.h>
#include <math.h>

#define SQ 2048
#define NB 8
#define HDIM 768
#define HD 384
#define NG 1536
#define NT 64
#define NU 32

// ---------------- device scratch (static, no runtime alloc) ----------------
__device__ float    g_xproj[2u * SQ * NB * NG];   // [dir][t][b][gate_row]
__device__ float    g_hbuf [8 * 2 * 2 * HD];      // fallback path exchange
__device__ unsigned g_flag [128 * 32];            // fallback path flags
__device__ float    g_mp   [NB * NU * HDIM];      // [b][u][h] pooled features
__device__ float    g_emb  [NB * NU * HDIM];      // [b][u][h] routed embeddings

// ---------------- helpers ---------------------------------------------------
__device__ __forceinline__ unsigned long long fma2(
    unsigned long long a, unsigned long long b, unsigned long long c) {
    unsigned long long d;
    asm("fma.rn.f32x2 %0, %1, %2, %3;" : "=l"(d) : "l"(a), "l"(b), "l"(c));
    return d;
}
__device__ __forceinline__ float2 upk2(unsigned long long v) {
    float2 f;
    asm("mov.b64 {%0,%1}, %2;" : "=f"(f.x), "=f"(f.y) : "l"(v));
    return f;
}
__device__ __forceinline__ unsigned smem_u32(const void* p) {
    unsigned a;
    asm("{ .reg .u64 t; cvta.to.shared.u64 t, %1; cvt.u32.u64 %0, t; }"
        : "=r"(a) : "l"(p));
    return a;
}
__device__ __forceinline__ void mbar_wait(unsigned addr, unsigned phase) {
    unsigned done;
    do {
        asm volatile(
            "{\n\t.reg .pred p;\n\t"
            "mbarrier.try_wait.parity.acquire.cta.shared::cta.b64 p, [%1], %2, 0x989680;\n\t"
            "selp.b32 %0, 1, 0, p;\n\t}"
            : "=r"(done) : "r"(addr), "r"(phase) : "memory");
    } while (!done);
}

// ---------------- pad kernel (ncu steering: launch #4 = lstm kernel) -------
__global__ void k_pad() {}

// ---------------- flag reset (fallback path only) --------------------------
__global__ void k_reset()
{
    int i = blockIdx.x * 256 + threadIdx.x;
    if (i < 128 * 32) g_flag[i] = 0u;
}

// ---------------- K1: input projection GEMM (R1/R8 version — known good) ---
__global__ void __launch_bounds__(256) k_gemm(
    const float* __restrict__ X,
    const float* __restrict__ Wf, const float* __restrict__ Wb,
    const float* __restrict__ bihf, const float* __restrict__ bhhf,
    const float* __restrict__ bihb, const float* __restrict__ bhhb)
{
    const int dir = blockIdx.z;
    const float* W = dir ? Wb : Wf;
    const int n0 = blockIdx.x * 128;
    const int m0 = blockIdx.y * 128;

    __shared__ float As[8][128];
    __shared__ float Bs[8][128];

    const int tid = threadIdx.x;
    const int lr = tid >> 1, lh = tid & 1;
    const int tx = tid & 15, ty = tid >> 4;

    float acc[8][8];
#pragma unroll
    for (int i = 0; i < 8; i++)
#pragma unroll
        for (int j = 0; j < 8; j++) acc[i][j] = 0.f;

    const float* xptr = X + (m0 + lr) * 768 + lh * 4;
    const float* wptr = W + (n0 + lr) * 768 + lh * 4;

    for (int kt = 0; kt < 768; kt += 8) {
        float4 av = *(const float4*)(xptr + kt);
        float4 bv = *(const float4*)(wptr + kt);
        __syncthreads();
        As[lh * 4 + 0][lr] = av.x; As[lh * 4 + 1][lr] = av.y;
        As[lh * 4 + 2][lr] = av.z; As[lh * 4 + 3][lr] = av.w;
        Bs[lh * 4 + 0][lr] = bv.x; Bs[lh * 4 + 1][lr] = bv.y;
        Bs[lh * 4 + 2][lr] = bv.z; Bs[lh * 4 + 3][lr] = bv.w;
        __syncthreads();
#pragma unroll
        for (int k = 0; k < 8; k++) {
            float a[8], b[8];
            *(float4*)(a)     = *(const float4*)&As[k][ty * 8];
            *(float4*)(a + 4) = *(const float4*)&As[k][ty * 8 + 4];
            *(float4*)(b)     = *(const float4*)&Bs[k][tx * 8];
            *(float4*)(b + 4) = *(const float4*)&Bs[k][tx * 8 + 4];
#pragma unroll
            for (int i = 0; i < 8; i++)
#pragma unroll
                for (int j = 0; j < 8; j++)
                    acc[i][j] = fmaf(a[i], b[j], acc[i][j]);
        }
    }

    const float* bi = dir ? bihb : bihf;
    const float* bh = dir ? bhhb : bhhf;
    float bias[8];
#pragma unroll
    for (int j = 0; j < 8; j++) {
        int n = n0 + tx * 8 + j;
        bias[j] = bi[n] + bh[n];
    }
#pragma unroll
    for (int i = 0; i < 8; i++) {
        int m = m0 + ty * 8 + i;
        int s = m & 2047, bb = m >> 11;
        int t = dir ? (2047 - s) : s;
        float* o = g_xproj + ((((dir * SQ + t) * NB + bb) * NG) + n0 + tx * 8);
        float4 v0, v1;
        v0.x = acc[i][0] + bias[0]; v0.y = acc[i][1] + bias[1];
        v0.z = acc[i][2] + bias[2]; v0.w = acc[i][3] + bias[3];
        v1.x = acc[i][4] + bias[4]; v1.y = acc[i][5] + bias[5];
        v1.z = acc[i][6] + bias[6]; v1.w = acc[i][7] + bias[7];
        *(float4*)(o)     = v0;
        *(float4*)(o + 4) = v1;
    }
}

// ---------------- K2a: cluster BiLSTM (DSMEM st.async exchange) ------------
// 8 clusters of 16 CTAs = (dir, batch-pair) groups. CTA rank c owns units
// [24c, 24c+24), 4 gates, 2 batches; weights in registers. h exchanged by
// st.async into all 16 peers' double-buffered h_s, completion via mbarrier
// expect_tx (3072B = 16 CTAs x 48 floats). Recurrence dataflow provides
// backpressure; clusters are mutually independent (wave execution is safe).
__global__ void __launch_bounds__(256, 1) __cluster_dims__(16, 1, 1)
k_lstm_cl(const float* __restrict__ Whhf, const float* __restrict__ Whhb,
          const int* __restrict__ utter)
{
    unsigned c;
    asm("mov.u32 %0, %%cluster_ctarank;" : "=r"(c));
    const int grp = blockIdx.x >> 4;
    const int dir = grp >> 2;
    const int bp  = grp & 3;
    const int j0  = (int)c * 24;
    const float* Whh = dir ? Whhb : Whhf;
    const int tid = threadIdx.x;
    const int wid = tid >> 5, lane = tid & 31;
    const int g2   = wid >> 1;
    const int half = wid & 1;
    const int jw   = j0 + half * 12;

    __shared__ __align__(16) float h_s[2][2][HD];   // [buf][b2][j]
    __shared__ float gate_s[4][24][2];
    __shared__ float segmax_s[2][33][24];
    __shared__ __align__(8) unsigned long long mbar[2];

    for (int i = tid; i < 2 * 2 * HD; i += 256) (&h_s[0][0][0])[i] = 0.f;
    for (int i = tid; i < 2 * 33 * 24; i += 256) (&segmax_s[0][0][0])[i] = 0.f;

    const unsigned mb0 = smem_u32(&mbar[0]);
    const unsigned mb1 = smem_u32(&mbar[1]);
    if (tid == 0) {
        asm volatile("mbarrier.init.shared.b64 [%0], %1;" :: "r"(mb0), "r"(1u) : "memory");
        asm volatile("mbarrier.init.shared.b64 [%0], %1;" :: "r"(mb1), "r"(1u) : "memory");
    }
    __syncthreads();
    if (tid == 0) {   // arm both buffers for h(0), h(1)
        asm volatile("mbarrier.arrive.expect_tx.shared.b64 _, [%0], %1;" :: "r"(mb0), "r"(3072u) : "memory");
        asm volatile("mbarrier.arrive.expect_tx.shared.b64 _, [%0], %1;" :: "r"(mb1), "r"(3072u) : "memory");
    }

    // weights: wp[i][q] = Whh[(g2*HD + jw + i)*HD + lane*2 + 64q]  (f32x2)
    unsigned long long wp[12][6];
#pragma unroll
    for (int i = 0; i < 12; i++) {
        const float* wr = Whh + (long)(g2 * HD + jw + i) * HD + lane * 2;
#pragma unroll
        for (int q = 0; q < 6; q++)
            wp[i][q] = *(const unsigned long long*)(wr + 64 * q);
    }

    const int jj_a = tid >> 1, b2_a = tid & 1;
    const int batch_a = bp * 2 + b2_a;
    float c_state = 0.f;

    __syncthreads();
    asm volatile("barrier.cluster.arrive.aligned;" ::: "memory");
    asm volatile("barrier.cluster.wait.aligned;" ::: "memory");

    for (int t = 0; t < SQ; t++) {
        // prefetch xproj + utterance id (overlaps the wait + FMA phase)
        float xp0 = 0.f, xp1 = 0.f, xp2 = 0.f, xp3 = 0.f;
        int useg = 0;
        if (tid < 48) {
            int pos = dir ? (SQ - 1 - t) : t;
            const float* xb = g_xproj +
                ((((long)dir * SQ + t) * NB + batch_a) * NG) + j0 + jj_a;
            xp0 = xb[0]; xp1 = xb[HD]; xp2 = xb[2 * HD]; xp3 = xb[3 * HD];
            int u = utter[batch_a * SQ + pos];
            useg = u > 0 ? u : 0;
        }

        // wait for h(t-1), then re-arm that mbar for h(t+1)
        if (t > 0) {
            unsigned mb = ((t - 1) & 1) ? mb1 : mb0;
            mbar_wait(mb, ((unsigned)(t - 1) >> 1) & 1u);
            if (tid == 0)
                asm volatile("mbarrier.arrive.expect_tx.shared.b64 _, [%0], %1;"
                             :: "r"(mb), "r"(3072u) : "memory");
        }

        // gate FMA on h(t-1) in buf (t+1)&1
        const int br = (t + 1) & 1;
#pragma unroll
        for (int b2 = 0; b2 < 2; b2++) {
            unsigned long long p2[12];
#pragma unroll
            for (int i = 0; i < 12; i++) p2[i] = 0ull;
#pragma unroll
            for (int q = 0; q < 6; q++) {
                unsigned long long hq =
                    *(const unsigned long long*)&h_s[br][b2][lane * 2 + 64 * q];
#pragma unroll
                for (int i = 0; i < 12; i++)
                    p2[i] = fma2(wp[i][q], hq, p2[i]);
            }
#pragma unroll
            for (int i = 0; i < 12; i++) {
                float2 f = upk2(p2[i]);
                float v = f.x + f.y;
                v += __shfl_xor_sync(0xffffffffu, v, 16);
                v += __shfl_xor_sync(0xffffffffu, v, 8);
                v += __shfl_xor_sync(0xffffffffu, v, 4);
                v += __shfl_xor_sync(0xffffffffu, v, 2);
                v += __shfl_xor_sync(0xffffffffu, v, 1);
                if (lane == 0) gate_s[g2][half * 12 + i][b2] = v;
            }
        }
        __syncthreads();

        // activation + DSMEM broadcast + fused segment max
        if (tid < 48) {
            float vi = gate_s[0][jj_a][b2_a] + xp0;
            float vf = gate_s[1][jj_a][b2_a] + xp1;
            float vg = gate_s[2][jj_a][b2_a] + xp2;
            float vo = gate_s[3][jj_a][b2_a] + xp3;
            float si = 1.f / (1.f + __expf(-vi));
            float sf = 1.f / (1.f + __expf(-vf));
            float so = 1.f / (1.f + __expf(-vo));
            float tg, tc;
            asm("tanh.approx.f32 %0, %1;" : "=f"(tg) : "f"(vg));
            c_state = sf * c_state + si * tg;
            asm("tanh.approx.f32 %0, %1;" : "=f"(tc) : "f"(c_state));
            float h = so * tc;

            unsigned val   = __float_as_uint(h);
            unsigned laddr = smem_u32(&h_s[t & 1][b2_a][j0 + jj_a]);
            unsigned lmbar = (t & 1) ? mb1 : mb0;
#pragma unroll
            for (int p = 0; p < 16; p++) {
                unsigned ra, rb;
                asm("mapa.shared::cluster.u32 %0, %1, %2;" : "=r"(ra) : "r"(laddr), "r"(p));
                asm("mapa.shared::cluster.u32 %0, %1, %2;" : "=r"(rb) : "r"(lmbar), "r"(p));
                asm volatile(
                    "st.async.shared::cluster.mbarrier::complete_tx::bytes.u32 [%0], %1, [%2];"
                    :: "r"(ra), "r"(val), "r"(rb) : "memory");
            }
            float* sm = &segmax_s[b2_a][useg][jj_a];
            *sm = fmaxf(*sm, h);
        }
        // no further sync: next-step mbar wait can't pass until our own
        // act threads (which read gate_s) have sent their tx.
    }

    // drain: wait for the final h(2047) tx so no peer writes after our exit
    mbar_wait(mb1, ((unsigned)(SQ - 1) >> 1) & 1u);

    if (tid < 48) {
        for (int u = 1; u <= NU; u++)
            g_mp[(batch_a * NU + (u - 1)) * HDIM + dir * HD + j0 + jj_a] =
                segmax_s[b2_a][u][jj_a];
    }
}

// ---------------- K2b: fallback BiLSTM (R8 version, L2 flag exchange) ------
__global__ void __launch_bounds__(256, 1) k_lstm(
    const float* __restrict__ Whhf, const float* __restrict__ Whhb,
    const int* __restrict__ utter)
{
    const int grp = blockIdx.x >> 4;
    const int c   = blockIdx.x & 15;
    const int dir = grp >> 2;
    const int bp  = grp & 3;
    const int j0  = c * 24;
    const float* Whh = dir ? Whhb : Whhf;
    const int tid = threadIdx.x;
    const int wid = tid >> 5, lane = tid & 31;
    const int g2   = wid >> 1;
    const int half = wid & 1;
    const int jw   = j0 + half * 12;

    __shared__ __align__(16) float h_s[2][HD];
    __shared__ float gate_s[4][24][2];
    __shared__ float segmax_s[2][33][24];

    for (int i = tid; i < 2 * HD; i += 256) (&h_s[0][0])[i] = 0.f;
    for (int i = tid; i < 2 * 33 * 24; i += 256) (&segmax_s[0][0][0])[i] = 0.f;

    unsigned long long wp[12][6];
#pragma unroll
    for (int i = 0; i < 12; i++) {
        const float* wr = Whh + (long)(g2 * HD + jw + i) * HD + lane * 2;
#pragma unroll
        for (int q = 0; q < 6; q++)
            wp[i][q] = *(const unsigned long long*)(wr + 64 * q);
    }

    const int jj_a = tid >> 1, b2_a = tid & 1;
    const int batch_a = bp * 2 + b2_a;
    float c_state = 0.f;
    unsigned* flags = g_flag + grp * 16 * 32;
    float* hbase = g_hbuf + grp * 2 * 2 * HD;

    __syncthreads();

    for (int t = 0; t < SQ; t++) {
        float xp0 = 0.f, xp1 = 0.f, xp2 = 0.f, xp3 = 0.f;
        int useg = 0;
        if (tid < 48) {
            int pos = dir ? (SQ - 1 - t) : t;
            const float* xb = g_xproj +
                ((((long)dir * SQ + t) * NB + batch_a) * NG) + j0 + jj_a;
            xp0 = xb[0]; xp1 = xb[HD]; xp2 = xb[2 * HD]; xp3 = xb[3 * HD];
            int u = utter[batch_a * SQ + pos];
            useg = u > 0 ? u : 0;
        }

#pragma unroll
        for (int b2 = 0; b2 < 2; b2++) {
            unsigned long long p2[12];
#pragma unroll
            for (int i = 0; i < 12; i++) p2[i] = 0ull;
#pragma unroll
            for (int q = 0; q < 6; q++) {
                unsigned long long hq =
                    *(const unsigned long long*)&h_s[b2][lane * 2 + 64 * q];
#pragma unroll
                for (int i = 0; i < 12; i++)
                    p2[i] = fma2(wp[i][q], hq, p2[i]);
            }
#pragma unroll
            for (int i = 0; i < 12; i++) {
                float2 f = upk2(p2[i]);
                float v = f.x + f.y;
                v += __shfl_xor_sync(0xffffffffu, v, 16);
                v += __shfl_xor_sync(0xffffffffu, v, 8);
                v += __shfl_xor_sync(0xffffffffu, v, 4);
                v += __shfl_xor_sync(0xffffffffu, v, 2);
                v += __shfl_xor_sync(0xffffffffu, v, 1);
                if (lane == 0) gate_s[g2][half * 12 + i][b2] = v;
            }
        }
        __syncthreads();

        if (tid < 48) {
            float vi = gate_s[0][jj_a][b2_a] + xp0;
            float vf = gate_s[1][jj_a][b2_a] + xp1;
            float vg = gate_s[2][jj_a][b2_a] + xp2;
            float vo = gate_s[3][jj_a][b2_a] + xp3;
            float si = 1.f / (1.f + __expf(-vi));
            float sf = 1.f / (1.f + __expf(-vf));
            float so = 1.f / (1.f + __expf(-vo));
            float tg, tc;
            asm("tanh.approx.f32 %0, %1;" : "=f"(tg) : "f"(vg));
            c_state = sf * c_state + si * tg;
            asm("tanh.approx.f32 %0, %1;" : "=f"(tc) : "f"(c_state));
            float h = so * tc;
            __stcg(hbase + (t & 1) * 2 * HD + b2_a * HD + j0 + jj_a, h);
            float* sm = &segmax_s[b2_a][useg][jj_a];
            *sm = fmaxf(*sm, h);
        }
        __syncthreads();

        if (tid == 0) {
            asm volatile("st.release.gpu.global.u32 [%0], %1;"
                         :: "l"(flags + c * 32), "r"((unsigned)(t + 1)) : "memory");
        }
        if (wid == 0) {
            unsigned tgt = (unsigned)(t + 1);
            const unsigned* fp = flags + lane * 32;
            bool ok;
            do {
                unsigned v = tgt;
                if (lane < 16)
                    asm volatile("ld.acquire.gpu.global.u32 %0, [%1];"
                                 : "=r"(v) : "l"(fp) : "memory");
                ok = __all_sync(0xffffffffu, v >= tgt);
            } while (!ok);
        }
        __syncthreads();

        if (tid < 192) {
            const float4* src = (const float4*)(hbase + (t & 1) * 2 * HD);
            ((float4*)(&h_s[0][0]))[tid] = __ldcg(src + tid);
        }
        __syncthreads();
    }

    if (tid < 48) {
        for (int u = 1; u <= NU; u++)
            g_mp[(batch_a * NU + (u - 1)) * HDIM + dir * HD + j0 + jj_a] =
                segmax_s[b2_a][u][jj_a];
    }
}

// ---------------- K3: topic softmax routing ---------------------------------
__global__ void __launch_bounds__(256) k_route(
    const float* __restrict__ tw, const float* __restrict__ tb,
    const float* __restrict__ table)
{
    const int b = blockIdx.x >> 5;
    const int u = blockIdx.x & 31;
    __shared__ float mp_s[768];
    __shared__ float lp_s[4][64];
    __shared__ float l_s[64], e_s[64];
    const int tid = threadIdx.x;
    const float* mpr = g_mp + (b * NU + u) * HDIM;
    for (int i = tid; i < 192; i += 256)
        ((float4*)mp_s)[i] = ((const float4*)mpr)[i];
    __syncthreads();
    {
        const int topic = tid & 63, slice = tid >> 6;
        float acc = 0.f;
        const float* wr = tw + topic * 768 + slice * 192;
        const float* ms = mp_s + slice * 192;
        for (int k = 0; k < 192; k += 4) {
            float4 wv = *(const float4*)(wr + k);
            acc = fmaf(wv.x, ms[k], acc);
            acc = fmaf(wv.y, ms[k + 1], acc);
            acc = fmaf(wv.z, ms[k + 2], acc);
            acc = fmaf(wv.w, ms[k + 3], acc);
        }
        lp_s[slice][topic] = acc;
    }
    __syncthreads();
    if (tid < 64)
        l_s[tid] = lp_s[0][tid] + lp_s[1][tid] + lp_s[2][tid] + lp_s[3][tid] + tb[tid];
    __syncthreads();
    if (tid < 64) {
        float mx = -1e30f;
        for (int i = 0; i < 64; i++) mx = fmaxf(mx, l_s[i]);
        e_s[tid] = expf(l_s[tid] - mx);
    }
    __syncthreads();
    float ssum = 0.f;
    for (int i = 0; i < 64; i++) ssum += e_s[i];
    float inv = 1.f / ssum;
    for (int h = tid; h < 768; h += 256) {
        float acc = 0.f;
        for (int tt = 0; tt < 64; tt++)
            acc = fmaf(e_s[tt], table[tt * 768 + h], acc);
        g_emb[(b * NU + u) * HDIM + h] = acc * inv;
    }
}

// ---------------- K4: scatter back to token positions -----------------------
__global__ void __launch_bounds__(256) k_scatter(
    const int* __restrict__ utter, float* __restrict__ out)
{
    int v = blockIdx.x * 256 + threadIdx.x;
    int m = v / 192;
    int h4 = v - m * 192;
    int u = __ldg(utter + m);
    float4 o = make_float4(0.f, 0.f, 0.f, 0.f);
    if (u != 0) {
        int idx = u > 0 ? u - 1 : -u - 1;
        if (idx > 31) idx = 31;
        int bb = m >> 11;
        float4 gv = *(const float4*)(g_emb + (bb * NU + idx) * HDIM + h4 * 4);
        float sc = u > 0 ? 1.f : 2.f;
        o.x = gv.x * sc; o.y = gv.y * sc; o.z = gv.z * sc; o.w = gv.w * sc;
    }
    ((float4*)out)[v] = o;
}

// ---------------- launch -----------------------------------------------------
extern "C" void kernel_launch(void* const* d_in, const int* in_sizes, int n_in,
                              void* d_out, int out_size)
{
    const float* X     = (const float*)d_in[0];
    const float* Wihf  = (const float*)d_in[1];
    const float* Whhf  = (const float*)d_in[2];
    const float* bihf  = (const float*)d_in[3];
    const float* bhhf  = (const float*)d_in[4];
    const float* Wihb  = (const float*)d_in[5];
    const float* Whhb  = (const float*)d_in[6];
    const float* bihb  = (const float*)d_in[7];
    const float* bhhb  = (const float*)d_in[8];
    const float* tw    = (const float*)d_in[9];
    const float* tb    = (const float*)d_in[10];
    const float* table = (const float*)d_in[11];
    const int*   utter = (const int*)d_in[12];

    // probe: clusters are mutually independent, so ncl >= 4 (2 waves) already
    // beats the L2-flag fallback. Probe WITHOUT cluster attrs first (the
    // kernel carries compile-time __cluster_dims__; passing the attr too can
    // be rejected as a config conflict), then with attrs as a fallback.
    cudaFuncSetAttribute(k_lstm_cl,
                         cudaFuncAttributeNonPortableClusterSizeAllowed, 1);
    int ncl = 0;
    {
        cudaLaunchConfig_t cfg = {};
        cfg.gridDim  = dim3(128, 1, 1);
        cfg.blockDim = dim3(256, 1, 1);
        cfg.dynamicSmemBytes = 0;
        cfg.stream = 0;
        cfg.attrs = 0;
        cfg.numAttrs = 0;
        cudaError_t e1 = cudaOccupancyMaxActiveClusters(&ncl, k_lstm_cl, &cfg);
        if (e1 != cudaSuccess || ncl <= 0) {
            cudaGetLastError();
            cudaLaunchAttribute a[1];
            a[0].id = cudaLaunchAttributeClusterDimension;
            a[0].val.clusterDim.x = 16;
            a[0].val.clusterDim.y = 1;
            a[0].val.clusterDim.z = 1;
            cfg.attrs = a;
            cfg.numAttrs = 1;
            ncl = 0;
            cudaError_t e2 = cudaOccupancyMaxActiveClusters(&ncl, k_lstm_cl, &cfg);
            if (e2 != cudaSuccess) ncl = 0;
        }
        cudaGetLastError();   // clear any sticky probe error
    }
    bool use_cl = (ncl >= 4);

    // 2 pads: ncu capture (launch #4) lands on the lstm kernel (cluster path)
    // or on k_reset (fallback path) — a free path indicator.
    k_pad<<<1, 32>>>();
    k_pad<<<1, 32>>>();
    k_gemm<<<dim3(12, 128, 2), 256>>>(X, Wihf, Wihb, bihf, bhhf, bihb, bhhb);
    if (use_cl) {
        k_lstm_cl<<<128, 256>>>(Whhf, Whhb, utter);   // cluster dims from annotation
    } else {
        k_reset<<<16, 256>>>();
        k_lstm<<<128, 256>>>(Whhf, Whhb, utter);
    }
    k_route<<<256, 256>>>(tw, tb, table);
    k_scatter<<<12288, 256>>>(utter, (float*)d_out);
}